// round 1
// baseline (speedup 1.0000x reference)
#include <cuda_runtime.h>
#include <cuda_fp16.h>

// Problem constants
#define Bn   64
#define Rn   4608
#define Cn   32
#define INn  8
#define OUTn 16
#define RCHUNK 64
#define NCHUNK 72   // Rn / RCHUNK

// Scratch (device globals: allocation-free per harness rules)
static __device__ __half g_uhat[(size_t)Bn * Cn * Rn * OUTn];          // 302 MB fp16
static __device__ float  g_part[(size_t)Cn * NCHUNK * Bn * OUTn];      // iter-1 partial sums (exact fp32)

// ---- packed f32x2 helpers (sm_100+) ----
__device__ __forceinline__ unsigned long long pk2(float lo, float hi) {
    unsigned long long r;
    asm("mov.b64 %0, {%1, %2};" : "=l"(r) : "f"(lo), "f"(hi));
    return r;
}
__device__ __forceinline__ unsigned long long ffma2(unsigned long long a, unsigned long long b, unsigned long long c) {
    unsigned long long d;
    asm("fma.rn.f32x2 %0, %1, %2, %3;" : "=l"(d) : "l"(a), "l"(b), "l"(c));
    return d;
}
__device__ __forceinline__ float2 upk2(unsigned long long v) {
    float lo, hi;
    asm("mov.b64 {%0, %1}, %2;" : "=f"(lo), "=f"(hi) : "l"(v));
    return make_float2(lo, hi);
}

// ============================================================================
// Kernel 1: u_hat (fp16) + exact fp32 partial sums for iteration-1 mean.
// Grid: (Cn, NCHUNK). Block: 256 threads = 4 r-groups x 64 batches.
// Warp lanes = consecutive b with identical r -> smem W reads broadcast.
// ============================================================================
__global__ void __launch_bounds__(256)
k1_uhat(const float* __restrict__ x, const float* __restrict__ w) {
    const int c     = blockIdx.x;
    const int chunk = blockIdx.y;
    const int r0    = chunk * RCHUNK;
    const int tid   = threadIdx.x;

    __shared__ float sW[RCHUNK * 128];   // 32 KB: W[r0..r0+63][c][i][o]

    // Stage W chunk (coalesced float4 copies)
    {
        const float4* wg = reinterpret_cast<const float4*>(w);
        float4*       ws = reinterpret_cast<float4*>(sW);
        #pragma unroll
        for (int t = tid; t < RCHUNK * 32; t += 256) {
            int rr = t >> 5;
            int q  = t & 31;
            ws[rr * 32 + q] = wg[((size_t)(r0 + rr) * Cn + c) * 32 + q];
        }
    }
    __syncthreads();

    const int rgroup = tid >> 6;       // 0..3
    const int bb     = tid & 63;       // batch (lane-contiguous)
    const int rs     = rgroup * (RCHUNK / 4);

    float sacc[OUTn];
    #pragma unroll
    for (int o = 0; o < OUTn; o++) sacc[o] = 0.f;

    for (int k = 0; k < RCHUNK / 4; k++) {
        const int rr = rs + k;
        const int r  = r0 + rr;

        // x row (8 floats)
        const float4* xg = reinterpret_cast<const float4*>(x + ((size_t)bb * Rn + r) * INn);
        float4 x0 = xg[0], x1 = xg[1];
        float xv[8] = {x0.x, x0.y, x0.z, x0.w, x1.x, x1.y, x1.z, x1.w};

        unsigned long long acc[8];
        #pragma unroll
        for (int j = 0; j < 8; j++) acc[j] = 0ull;  // (+0.f, +0.f)

        const unsigned long long* wr =
            reinterpret_cast<const unsigned long long*>(sW + rr * 128);
        #pragma unroll
        for (int i = 0; i < 8; i++) {
            unsigned long long x2 = pk2(xv[i], xv[i]);
            #pragma unroll
            for (int j = 0; j < 8; j++) {
                acc[j] = ffma2(x2, wr[i * 8 + j], acc[j]);   // broadcast LDS.64
            }
        }

        // convert to fp16, accumulate iter-1 sums, store 32B
        union { __half2 h[8]; uint4 q[2]; } cv;
        #pragma unroll
        for (int j = 0; j < 8; j++) {
            float2 u = upk2(acc[j]);
            sacc[2 * j]     += u.x;
            sacc[2 * j + 1] += u.y;
            cv.h[j] = __floats2half2_rn(u.x, u.y);
        }
        uint4* dst = reinterpret_cast<uint4*>(
            g_uhat + (((size_t)bb * Cn + c) * Rn + r) * OUTn);
        dst[0] = cv.q[0];
        dst[1] = cv.q[1];
    }

    // Reduce sacc across the 4 r-groups per batch (reuse sW, fixed order)
    __syncthreads();
    float* sred = sW;                       // 256*16 floats = 16 KB <= 32 KB
    #pragma unroll
    for (int o = 0; o < OUTn; o++) sred[tid * OUTn + o] = sacc[o];
    __syncthreads();
    if (tid < 64) {
        #pragma unroll
        for (int o = 0; o < OUTn; o++) {
            float s = sred[tid * OUTn + o]
                    + sred[(64  + tid) * OUTn + o]
                    + sred[(128 + tid) * OUTn + o]
                    + sred[(192 + tid) * OUTn + o];
            g_part[(((size_t)c * NCHUNK + chunk) * Bn + tid) * OUTn + o] = s;
        }
    }
}

// ============================================================================
// Kernel 2: routing. One CTA per (b,c). v1 from exact partials, then two
// streaming passes over fp16 u_hat with plain-exp softmax (logits bounded).
// All reductions are fixed-order -> deterministic.
// ============================================================================
__global__ void __launch_bounds__(256)
k2_route(float* __restrict__ out) {
    const int bc  = blockIdx.x;
    const int bb  = bc >> 5;          // / Cn
    const int c   = bc & (Cn - 1);
    const int tid = threadIdx.x;

    __shared__ float s_tmp[16 * 17];  // staged partial reductions
    __shared__ float s_v[OUTn];       // current v (broadcast)

    // ---- iteration 1: v1 = squash(mean_r u_r) from exact fp32 partials ----
    {
        const int j = tid >> 4;       // 0..15
        const int o = tid & 15;
        float acc = 0.f;
        for (int cn = j; cn < NCHUNK; cn += 16)
            acc += g_part[(((size_t)c * NCHUNK + cn) * Bn + bb) * OUTn + o];
        s_tmp[j * 17 + o] = acc;
    }
    __syncthreads();
    if (tid == 0) {
        float sv[OUTn];
        float sq = 0.f;
        #pragma unroll
        for (int o = 0; o < OUTn; o++) {
            float S = 0.f;
            for (int j = 0; j < 16; j++) S += s_tmp[j * 17 + o];
            S *= (1.0f / Rn);
            sv[o] = S;
            sq += S * S;
        }
        float coef = (sq / (1.f + sq)) / sqrtf(sq + 1e-8f);
        #pragma unroll
        for (int o = 0; o < OUTn; o++) s_v[o] = sv[o] * coef;
    }
    __syncthreads();

    float vcur[OUTn];                  // logit vector: v1, then v1+v2
    #pragma unroll
    for (int o = 0; o < OUTn; o++) vcur[o] = s_v[o];

    const __half* ub = g_uhat + (((size_t)bb * Cn + c) * Rn) * OUTn;

    for (int pass = 0; pass < 2; pass++) {
        float d = 0.f;
        float n[OUTn];
        #pragma unroll
        for (int o = 0; o < OUTn; o++) n[o] = 0.f;

        #pragma unroll 2
        for (int k = 0; k < Rn / 256; k++) {
            const int r = k * 256 + tid;
            const uint4* p = reinterpret_cast<const uint4*>(ub + (size_t)r * OUTn);
            union { __half2 h[8]; uint4 q[2]; } cv;
            cv.q[0] = p[0];
            cv.q[1] = p[1];
            float u[OUTn];
            #pragma unroll
            for (int j = 0; j < 8; j++) {
                float2 f = __half22float2(cv.h[j]);
                u[2 * j] = f.x;
                u[2 * j + 1] = f.y;
            }
            float t = 0.f;
            #pragma unroll
            for (int o = 0; o < OUTn; o++) t = fmaf(u[o], vcur[o], t);
            float e = __expf(t);       // |t| <~ 60: no overflow, no max needed
            d += e;
            #pragma unroll
            for (int o = 0; o < OUTn; o++) n[o] = fmaf(e, u[o], n[o]);
        }

        // block reduction of (d, n[16]) — warp shfl then smem, fixed order
        #pragma unroll
        for (int off = 16; off; off >>= 1) {
            d += __shfl_xor_sync(0xffffffffu, d, off);
            #pragma unroll
            for (int o = 0; o < OUTn; o++)
                n[o] += __shfl_xor_sync(0xffffffffu, n[o], off);
        }
        const int warp = tid >> 5, lane = tid & 31;
        __syncthreads();                       // prior s_tmp consumers done
        if (lane == 0) {
            s_tmp[warp * 17 + 16] = d;
            #pragma unroll
            for (int o = 0; o < OUTn; o++) s_tmp[warp * 17 + o] = n[o];
        }
        __syncthreads();
        if (tid == 0) {
            float D = 0.f;
            for (int wv = 0; wv < 8; wv++) D += s_tmp[wv * 17 + 16];
            float sv[OUTn];
            float sq = 0.f;
            #pragma unroll
            for (int o = 0; o < OUTn; o++) {
                float S = 0.f;
                for (int wv = 0; wv < 8; wv++) S += s_tmp[wv * 17 + o];
                S /= D;
                sv[o] = S;
                sq += S * S;
            }
            float coef = (sq / (1.f + sq)) / sqrtf(sq + 1e-8f);
            #pragma unroll
            for (int o = 0; o < OUTn; o++) s_v[o] = sv[o] * coef;
        }
        __syncthreads();

        if (pass == 0) {
            #pragma unroll
            for (int o = 0; o < OUTn; o++) vcur[o] += s_v[o];   // v1 + v2
        } else {
            if (tid < OUTn)
                out[((size_t)bb * Cn + c) * OUTn + tid] = s_v[tid];
        }
    }
}

// ============================================================================
extern "C" void kernel_launch(void* const* d_in, const int* in_sizes, int n_in,
                              void* d_out, int out_size) {
    const float* x = (const float*)d_in[0];           // (64, 4608, 8)
    const float* w = (const float*)d_in[1];           // (4608, 32, 8, 16)
    float* out = (float*)d_out;                       // (64, 32, 16)

    dim3 g1(Cn, NCHUNK);
    k1_uhat<<<g1, 256>>>(x, w);
    k2_route<<<Bn * Cn, 256>>>(out);
}

// round 2
// speedup vs baseline: 1.4983x; 1.4983x over previous
#include <cuda_runtime.h>
#include <cuda_fp16.h>

// Problem constants
#define Bn   64
#define Rn   4608
#define Cn   32
#define INn  8
#define OUTn 16
#define RCHUNK 64
#define NCHUNK 72    // Rn / RCHUNK
#define RPASS  128
#define NSPLIT 36    // Rn / RPASS

// Scratch (device globals; allocation-free per harness rules)
// u_hat layout: [c][r][h(2)][b(64)] of uint4 (8 fp16 each) -> dense 512B warp accesses
static __device__ uint4  g_uhat4[(size_t)Cn * Rn * 2 * Bn];          // 302 MB
static __device__ float4 g_xT4[(size_t)Rn * 2 * Bn];                 // x transposed: [r][h][b] float4
static __device__ float  g_part[(size_t)Cn * NCHUNK * Bn * OUTn];    // iter-1 partial sums
static __device__ float  g_red[(size_t)Cn * NSPLIT * Bn * 17];       // pass partials (n[16], d)
static __device__ float  g_v1[(size_t)Bn * Cn * OUTn];
static __device__ float  g_vcur[(size_t)Bn * Cn * OUTn];             // current logit vector

// ---- packed f32x2 helpers ----
__device__ __forceinline__ unsigned long long pk2(float lo, float hi) {
    unsigned long long r;
    asm("mov.b64 %0, {%1, %2};" : "=l"(r) : "f"(lo), "f"(hi));
    return r;
}
__device__ __forceinline__ unsigned long long ffma2(unsigned long long a, unsigned long long b, unsigned long long c) {
    unsigned long long d;
    asm("fma.rn.f32x2 %0, %1, %2, %3;" : "=l"(d) : "l"(a), "l"(b), "l"(c));
    return d;
}
__device__ __forceinline__ float2 upk2(unsigned long long v) {
    float lo, hi;
    asm("mov.b64 {%0, %1}, %2;" : "=f"(lo), "=f"(hi) : "l"(v));
    return make_float2(lo, hi);
}

// ============================================================================
// k0: transpose x (64 b, 9216 float4) -> xT (9216 float4-rows, 64 b).
// Classic 32x32 float4 tile, smem padded. Grid (288, 2), block (32, 8).
// ============================================================================
__global__ void __launch_bounds__(256)
k0_transpose(const float4* __restrict__ x4) {
    __shared__ float4 tile[32][33];
    const int f0 = blockIdx.x * 32;
    const int b0 = blockIdx.y * 32;
    const int tx = threadIdx.x;
    const int ty0 = threadIdx.y;
    #pragma unroll
    for (int j = 0; j < 4; j++) {
        int ty = ty0 * 4 + j;
        tile[ty][tx] = x4[(size_t)(b0 + ty) * (Rn * 2) + f0 + tx];
    }
    __syncthreads();
    #pragma unroll
    for (int j = 0; j < 4; j++) {
        int ty = ty0 * 4 + j;
        g_xT4[(size_t)(f0 + ty) * Bn + b0 + tx] = tile[tx][ty];
    }
}

// ============================================================================
// k1: u_hat (fp16) + exact fp32 partial sums for the iteration-1 mean.
// Grid (Cn, NCHUNK), block 256 = 4 r-groups x 64 batches (lane = batch).
// W staged in smem (broadcast reads), x from xT (dense), stores dense.
// ============================================================================
__global__ void __launch_bounds__(256)
k1_uhat(const float* __restrict__ w) {
    const int c     = blockIdx.x;
    const int chunk = blockIdx.y;
    const int r0    = chunk * RCHUNK;
    const int tid   = threadIdx.x;

    __shared__ float sW[RCHUNK * 128];   // 32 KB: W[r0..r0+63][c][i][o]

    {
        const float4* wg = reinterpret_cast<const float4*>(w);
        float4*       ws = reinterpret_cast<float4*>(sW);
        #pragma unroll
        for (int t = tid; t < RCHUNK * 32; t += 256) {
            int rr = t >> 5;
            int q  = t & 31;
            ws[rr * 32 + q] = wg[((size_t)(r0 + rr) * Cn + c) * 32 + q];
        }
    }
    __syncthreads();

    const int rgroup = tid >> 6;       // 0..3
    const int bb     = tid & 63;       // batch (lane-contiguous)

    float sacc[OUTn];
    #pragma unroll
    for (int o = 0; o < OUTn; o++) sacc[o] = 0.f;

    for (int k = 0; k < RCHUNK / 4; k++) {
        const int rr = rgroup * (RCHUNK / 4) + k;
        const int r  = r0 + rr;

        // x row (8 floats) — dense: lanes read consecutive float4
        float4 xa = g_xT4[((size_t)r * 2 + 0) * Bn + bb];
        float4 xb = g_xT4[((size_t)r * 2 + 1) * Bn + bb];
        float xv[8] = {xa.x, xa.y, xa.z, xa.w, xb.x, xb.y, xb.z, xb.w};

        unsigned long long acc[8];
        #pragma unroll
        for (int j = 0; j < 8; j++) acc[j] = 0ull;

        const unsigned long long* wr =
            reinterpret_cast<const unsigned long long*>(sW + rr * 128);
        #pragma unroll
        for (int i = 0; i < 8; i++) {
            unsigned long long x2 = pk2(xv[i], xv[i]);
            #pragma unroll
            for (int j = 0; j < 8; j++) {
                acc[j] = ffma2(x2, wr[i * 8 + j], acc[j]);   // broadcast LDS.64
            }
        }

        union { __half2 h[8]; uint4 q[2]; } cv;
        #pragma unroll
        for (int j = 0; j < 8; j++) {
            float2 u = upk2(acc[j]);
            sacc[2 * j]     += u.x;
            sacc[2 * j + 1] += u.y;
            cv.h[j] = __floats2half2_rn(u.x, u.y);
        }
        // dense stores: [c][r][h][b]
        size_t base = ((size_t)(c * Rn + r) * 2) * Bn + bb;
        g_uhat4[base]      = cv.q[0];
        g_uhat4[base + Bn] = cv.q[1];
    }

    // Reduce sacc across the 4 r-groups per batch (fixed order)
    __syncthreads();
    float* sred = sW;
    #pragma unroll
    for (int o = 0; o < OUTn; o++) sred[tid * OUTn + o] = sacc[o];
    __syncthreads();
    if (tid < 64) {
        #pragma unroll
        for (int o = 0; o < OUTn; o++) {
            float s = sred[tid * OUTn + o]
                    + sred[(64  + tid) * OUTn + o]
                    + sred[(128 + tid) * OUTn + o]
                    + sred[(192 + tid) * OUTn + o];
            g_part[(((size_t)c * NCHUNK + chunk) * Bn + tid) * OUTn + o] = s;
        }
    }
}

// ============================================================================
// kf_v1: v1 = squash(mean_r u_r) per (b,c); seeds g_vcur = v1.
// Grid Bn*Cn, block 32.
// ============================================================================
__global__ void __launch_bounds__(32)
kf_v1() {
    const int bc = blockIdx.x;
    const int b  = bc >> 5;
    const int c  = bc & 31;
    const int t  = threadIdx.x;

    float acc = 0.f;
    if (t < OUTn) {
        for (int ch = 0; ch < NCHUNK; ch++)
            acc += g_part[(((size_t)c * NCHUNK + ch) * Bn + b) * OUTn + t];
    }
    float val = (t < OUTn) ? acc * (1.0f / Rn) : 0.f;
    float sq = val * val;
    #pragma unroll
    for (int off = 16; off; off >>= 1) sq += __shfl_xor_sync(0xffffffffu, sq, off);
    float coef = (sq / (1.f + sq)) * rsqrtf(sq + 1e-8f);
    float v = val * coef;
    if (t < OUTn) {
        g_v1[(size_t)bc * OUTn + t]   = v;
        g_vcur[(size_t)bc * OUTn + t] = v;
    }
}

// ============================================================================
// k2p: one streaming routing pass. CTA = (c, 128-r slab). Lane = batch.
// Per-lane private (d, n[16]); softmax uses plain exp (logits bounded).
// Writes per-(c,slab,b) partials to g_red. Fixed-order -> deterministic.
// ============================================================================
__global__ void __launch_bounds__(256)
k2p() {
    const int c     = blockIdx.x;
    const int split = blockIdx.y;
    const int rbase = split * RPASS;
    const int tid   = threadIdx.x;
    const int warp  = tid >> 5;
    const int lane  = tid & 31;
    const int rgroup = warp >> 1;            // 0..3
    const int b      = (warp & 1) * 32 + lane;

    __shared__ float sV[Bn * OUTn];          // v for all 64 b of this c
    __shared__ float sRed[4 * Bn * 17];      // cross-rgroup reduction

    for (int t = tid; t < Bn * OUTn; t += 256) {
        int b_ = t >> 4, o_ = t & 15;
        sV[t] = g_vcur[((size_t)b_ * Cn + c) * OUTn + o_];
    }
    __syncthreads();

    float v[OUTn];
    #pragma unroll
    for (int o = 0; o < OUTn; o++) v[o] = sV[b * OUTn + o];

    float d = 0.f;
    float n[OUTn];
    #pragma unroll
    for (int o = 0; o < OUTn; o++) n[o] = 0.f;

    #pragma unroll 4
    for (int k = 0; k < RPASS / 4; k++) {
        const int r = rbase + rgroup * (RPASS / 4) + k;
        size_t base = ((size_t)(c * Rn + r) * 2) * Bn + b;
        uint4 q0 = g_uhat4[base];
        uint4 q1 = g_uhat4[base + Bn];
        union { __half2 h[8]; uint4 q[2]; } cv;
        cv.q[0] = q0;
        cv.q[1] = q1;
        float u[OUTn];
        #pragma unroll
        for (int j = 0; j < 8; j++) {
            float2 f = __half22float2(cv.h[j]);
            u[2 * j]     = f.x;
            u[2 * j + 1] = f.y;
        }
        float t = 0.f;
        #pragma unroll
        for (int o = 0; o < OUTn; o++) t = fmaf(u[o], v[o], t);
        float e = __expf(t);
        d += e;
        #pragma unroll
        for (int o = 0; o < OUTn; o++) n[o] = fmaf(e, u[o], n[o]);
    }

    float* sr = sRed + ((size_t)rgroup * Bn + b) * 17;
    #pragma unroll
    for (int o = 0; o < OUTn; o++) sr[o] = n[o];
    sr[16] = d;
    __syncthreads();

    if (tid < Bn) {
        #pragma unroll
        for (int o = 0; o < 17; o++) {
            float s = sRed[((0 * Bn + tid)) * 17 + o]
                    + sRed[((1 * Bn + tid)) * 17 + o]
                    + sRed[((2 * Bn + tid)) * 17 + o]
                    + sRed[((3 * Bn + tid)) * 17 + o];
            g_red[(((size_t)c * NSPLIT + split) * Bn + tid) * 17 + o] = s;
        }
    }
}

// ============================================================================
// kf_fin: reduce slab partials -> softmax-weighted sum -> squash.
// mode 0: g_vcur = v1 + v2 (logits for pass 2).  mode 1: write v3 to out.
// Grid Bn*Cn, block 32.
// ============================================================================
__global__ void __launch_bounds__(32)
kf_fin(int mode, float* __restrict__ out) {
    const int bc = blockIdx.x;
    const int b  = bc >> 5;
    const int c  = bc & 31;
    const int t  = threadIdx.x;

    float acc = 0.f;
    if (t < 17) {
        for (int s = 0; s < NSPLIT; s++)
            acc += g_red[(((size_t)c * NSPLIT + s) * Bn + b) * 17 + t];
    }
    float D = __shfl_sync(0xffffffffu, acc, 16);
    float val = (t < OUTn) ? acc / D : 0.f;
    float sq = val * val;
    #pragma unroll
    for (int off = 16; off; off >>= 1) sq += __shfl_xor_sync(0xffffffffu, sq, off);
    float coef = (sq / (1.f + sq)) * rsqrtf(sq + 1e-8f);
    float v = val * coef;
    if (t < OUTn) {
        if (mode == 0)
            g_vcur[(size_t)bc * OUTn + t] = g_v1[(size_t)bc * OUTn + t] + v;
        else
            out[(size_t)bc * OUTn + t] = v;
    }
}

// ============================================================================
extern "C" void kernel_launch(void* const* d_in, const int* in_sizes, int n_in,
                              void* d_out, int out_size) {
    const float* x = (const float*)d_in[0];           // (64, 4608, 8)
    const float* w = (const float*)d_in[1];           // (4608, 32, 8, 16)
    float* out = (float*)d_out;                       // (64, 32, 16)

    k0_transpose<<<dim3(Rn * 2 / 32, Bn / 32), dim3(32, 8)>>>((const float4*)x);
    k1_uhat<<<dim3(Cn, NCHUNK), 256>>>(w);
    kf_v1<<<Bn * Cn, 32>>>();
    k2p<<<dim3(Cn, NSPLIT), 256>>>();
    kf_fin<<<Bn * Cn, 32>>>(0, out);
    k2p<<<dim3(Cn, NSPLIT), 256>>>();
    kf_fin<<<Bn * Cn, 32>>>(1, out);
}